// round 13
// baseline (speedup 1.0000x reference)
#include <cuda_runtime.h>

#define NEG_INF (-3.4e38f)
#define CAP     8192              // max segment rows on the fast path
#define CAPW    (CAP / 32)        // bitmap words

// branchless per-element (max, argmax, tie) update — SELs, no branches
__device__ __forceinline__ void upd(float v, int r, float& m, int& idx, int& tie) {
    bool gt = v > m;
    bool eq = v == m;
    idx = gt ? r : idx;
    tie = gt ? 0 : (eq ? 1 : tie);
    m   = fmaxf(m, v);
}

__device__ __forceinline__ int lower_bound_batch(const int* bw, int N, int key, int is64) {
    int lo = 0, hi = N;
    while (lo < hi) {
        int mid = (lo + hi) >> 1;
        int v = is64 ? bw[2 * mid] : bw[mid];   // int64: low word == value
        if (v < key) lo = mid + 1; else hi = mid;
    }
    return lo;
}

// Fused single kernel: one CTA per segment; thread owns ONE scalar column, so
// the CTA streams its segment fully contiguously (whole 1KB rows, MLP=8).
// Matched rows = union of per-column argmax indices -> smem bitmap -> popc
// count -> write normalized attn directly. Ties at a column max (block-wide,
// ~1e-4 probability) or len>CAP -> exact rescan fallback vs smem column maxes.
__global__ __launch_bounds__(256, 8)
void segmax_fused_kernel(const float* __restrict__ x,
                         const int* __restrict__ batchw,
                         float* __restrict__ emb,
                         float* __restrict__ attn,
                         int N)
{
    __shared__ unsigned bm[CAPW];             // matched-row bitmap (1KB)
    __shared__ float    mfin[256];            // per-column segment max (1KB)
    __shared__ int      sh[4];                // 0=start 1=end 2=count 3=tie|is64<<1

    const int g   = blockIdx.x;
    const int tid = threadIdx.x;
    const int col = tid;

    for (int i = tid; i < CAPW; i += 256) bm[i] = 0;
    if (tid == 2) sh[2] = 0;
    // dtype detect: int64 viewed as 32-bit words -> word[N-1] is a high half == 0.
    if (tid == 3) sh[3] = (N >= 2 && batchw[N - 1] == 0) ? 2 : 0;
    __syncthreads();
    const int is64 = sh[3] >> 1;
    if (tid < 2) sh[tid] = lower_bound_batch(batchw, N, g + tid, is64);
    __syncthreads();
    const int start = sh[0];
    const int end   = sh[1];
    const int len   = end - start;

    // --- streaming pass: per-column (max, argmax, tie) ---
    float m = NEG_INF; int idx = -1; int tie = 0;
    {
        const float* p = x + (size_t)start * 256 + col;
        int r = start;
        for (; r + 7 < end; r += 8, p += 8 * 256) {   // 8 independent loads in flight
            float v0 = __ldcs(p);
            float v1 = __ldcs(p + 1 * 256);
            float v2 = __ldcs(p + 2 * 256);
            float v3 = __ldcs(p + 3 * 256);
            float v4 = __ldcs(p + 4 * 256);
            float v5 = __ldcs(p + 5 * 256);
            float v6 = __ldcs(p + 6 * 256);
            float v7 = __ldcs(p + 7 * 256);
            upd(v0, r,   m, idx, tie); upd(v1, r+1, m, idx, tie);
            upd(v2, r+2, m, idx, tie); upd(v3, r+3, m, idx, tie);
            upd(v4, r+4, m, idx, tie); upd(v5, r+5, m, idx, tie);
            upd(v6, r+6, m, idx, tie); upd(v7, r+7, m, idx, tie);
        }
        for (; r < end; r++, p += 256)
            upd(__ldcs(p), r, m, idx, tie);
    }

    emb[(size_t)g * 256 + col] = m;           // empty segment stays NEG_INF (== ref)
    mfin[tid] = m;
    if (tie && idx >= 0) atomicOr(&sh[3], 1); // block-wide tie flag
    __syncthreads();

    const bool fast = ((sh[3] & 1) == 0) && (len <= CAP);

    if (fast) {
        // mark argmax rows in bitmap
        if (idx >= 0) {
            int o = idx - start;
            atomicOr(&bm[o >> 5], 1u << (o & 31));
        }
        __syncthreads();
        // count distinct matched rows
        const int nwords = (len + 31) >> 5;
        int local = 0;
        for (int i = tid; i < nwords; i += 256) local += __popc(bm[i]);
        #pragma unroll
        for (int o = 16; o; o >>= 1) local += __shfl_down_sync(0xffffffffu, local, o);
        if ((tid & 31) == 0 && local) atomicAdd(&sh[2], local);
        __syncthreads();
        const float scale = 1.0f / fmaxf((float)sh[2], 1.0f);
        // write normalized attention (coalesced)
        for (int i = tid; i < len; i += 256) {
            unsigned bit = (bm[i >> 5] >> (i & 31)) & 1u;
            attn[start + i] = bit ? scale : 0.0f;
        }
    } else {
        // exact fallback: 8 warps, warp per row; lane checks 8 columns
        const int warp = tid >> 5;
        const int lane = tid & 31;
        int myCount = 0;
        for (int r = start + warp; r < end; r += 8) {
            const float* row = x + (size_t)r * 256;
            bool hit = false;
            #pragma unroll
            for (int c = 0; c < 8; c++) {
                int cc = lane + c * 32;
                hit |= (row[cc] == mfin[cc]);
            }
            unsigned h = __any_sync(0xffffffffu, hit);
            if (lane == 0) {
                myCount += h ? 1 : 0;
                attn[r] = h ? 1.0f : 0.0f;
            }
        }
        if (lane == 0 && myCount) atomicAdd(&sh[2], myCount);
        __syncthreads();
        const float scale = 1.0f / fmaxf((float)sh[2], 1.0f);
        for (int i = tid; i < len; i += 256)
            attn[start + i] *= scale;
    }
}

extern "C" void kernel_launch(void* const* d_in, const int* in_sizes, int n_in,
                              void* d_out, int out_size)
{
    const float* x      = (const float*)d_in[0];
    const int*   batchw = (const int*)d_in[1];

    const int N = in_sizes[1];
    const int D = in_sizes[0] / N;
    int G = (out_size - N) / D;               // layout: [emb (G*D) | attn (N)]
    if (G < 1) G = 1;

    float* emb  = (float*)d_out;
    float* attn = emb + (size_t)G * D;

    segmax_fused_kernel<<<G, 256>>>(x, batchw, emb, attn, N);
}

// round 14
// speedup vs baseline: 1.1253x; 1.1253x over previous
#include <cuda_runtime.h>

#define NEG_INF (-3.4e38f)
#define MAXG    65536
#define WCAP    24                // register-cached rows per lane in K2 (24*32=768)

__device__ int g_bounds[MAXG + 1];   // segment row bounds, published by K1

// branchless per-element (max, argmax, tie) update — SELs, no branches
__device__ __forceinline__ void upd(float v, int r, float& m, int& idx, int& tie) {
    bool gt = v > m;
    bool eq = v == m;
    idx = gt ? r : idx;
    tie = gt ? 0 : (eq ? 1 : tie);
    m   = fmaxf(m, v);
}

__device__ __forceinline__ int lower_bound_batch(const int* bw, int N, int key, int is64) {
    int lo = 0, hi = N;
    while (lo < hi) {
        int mid = (lo + hi) >> 1;
        int v = is64 ? bw[2 * mid] : bw[mid];   // int64: low word == value
        if (v < key) lo = mid + 1; else hi = mid;
    }
    return lo;
}

// K1 (UNCHANGED from R12 — proven codegen): one CTA per segment; thread owns
// ONE scalar column, CTA streams its segment fully contiguously (1KB rows).
// Branchless (max, argmax, tie); marks matched rows attn[row]=1.0f; publishes bounds.
__global__ __launch_bounds__(256, 8)
void segmax_mark_kernel(const float* __restrict__ x,
                        const int* __restrict__ batchw,
                        float* __restrict__ emb,
                        float* __restrict__ attn,
                        int N, int G)
{
    __shared__ int sh[4];                     // 0=start 1=end 2=is64
    const int g   = blockIdx.x;
    const int tid = threadIdx.x;
    const int col = tid;                      // scalar column 0..255

    // dtype detect: int64 viewed as 32-bit words -> word[N-1] is a high half == 0.
    if (tid == 2) sh[2] = (N >= 2 && batchw[N - 1] == 0) ? 1 : 0;
    __syncthreads();
    const int is64 = sh[2];
    if (tid < 2) sh[tid] = lower_bound_batch(batchw, N, g + tid, is64);
    __syncthreads();
    const int start = sh[0];
    const int end   = sh[1];

    if (tid == 0) {                           // publish bounds for K2
        g_bounds[g] = start;
        if (g == G - 1) g_bounds[G] = end;
    }

    float m = NEG_INF; int idx = -1; int tie = 0;
    {
        const float* p = x + (size_t)start * 256 + col;
        int r = start;
        for (; r + 7 < end; r += 8, p += 8 * 256) {   // MLP=8 independent loads
            float v0 = __ldcs(p);
            float v1 = __ldcs(p + 1 * 256);
            float v2 = __ldcs(p + 2 * 256);
            float v3 = __ldcs(p + 3 * 256);
            float v4 = __ldcs(p + 4 * 256);
            float v5 = __ldcs(p + 5 * 256);
            float v6 = __ldcs(p + 6 * 256);
            float v7 = __ldcs(p + 7 * 256);
            upd(v0, r,   m, idx, tie); upd(v1, r+1, m, idx, tie);
            upd(v2, r+2, m, idx, tie); upd(v3, r+3, m, idx, tie);
            upd(v4, r+4, m, idx, tie); upd(v5, r+5, m, idx, tie);
            upd(v6, r+6, m, idx, tie); upd(v7, r+7, m, idx, tie);
        }
        for (; r < end; r++, p += 256)
            upd(__ldcs(p), r, m, idx, tie);
    }

    emb[(size_t)g * 256 + col] = m;           // empty segment stays NEG_INF (== ref)

    if (!tie && idx >= 0) attn[idx] = 1.0f;   // mark matched row (idempotent)

    // rare: exact-bit tie at the column max -> warp-cooperative column rescan
    unsigned tmask = __ballot_sync(0xffffffffu, (tie != 0) && (idx >= 0));
    const int lane = tid & 31;
    while (tmask) {
        int L = __ffs(tmask) - 1; tmask &= tmask - 1;
        float mv   = __shfl_sync(0xffffffffu, m,   L);
        int   colL = __shfl_sync(0xffffffffu, col, L);
        for (int rr = start + lane; rr < end; rr += 32)
            if (x[(size_t)rr * 256 + colL] == mv) attn[rr] = 1.0f;
    }
}

// K2: warp per segment — no smem, no block syncs, one load round-trip.
// Count rows marked 1.0f via shuffle reduce, rewrite attn = mark ? 1/max(cnt,1) : 0.
// Replay-safe: marks are deterministic; stale values are 0 or scale != 1.0f.
__global__ __launch_bounds__(256)
void normalize_kernel(float* __restrict__ attn, int G)
{
    const int warp = threadIdx.x >> 5;
    const int lane = threadIdx.x & 31;
    const int g    = blockIdx.x * 8 + warp;
    if (g >= G) return;

    const int start = g_bounds[g];
    const int end   = g_bounds[g + 1];
    const int len   = end - start;

    if (len <= WCAP * 32) {                   // register-cached path (always, in practice)
        float vals[WCAP];
        int   local = 0, k = 0;
        for (int i = start + lane; i < end; i += 32, k++) {
            vals[k] = attn[i];
            local += (vals[k] == 1.0f) ? 1 : 0;
        }
        #pragma unroll
        for (int o = 16; o; o >>= 1) local += __shfl_xor_sync(0xffffffffu, local, o);
        const float scale = 1.0f / fmaxf((float)local, 1.0f);
        k = 0;
        for (int i = start + lane; i < end; i += 32, k++)
            attn[i] = (vals[k] == 1.0f) ? scale : 0.0f;
    } else {                                   // oversized segment fallback
        int local = 0;
        for (int i = start + lane; i < end; i += 32)
            local += (attn[i] == 1.0f) ? 1 : 0;
        #pragma unroll
        for (int o = 16; o; o >>= 1) local += __shfl_xor_sync(0xffffffffu, local, o);
        const float scale = 1.0f / fmaxf((float)local, 1.0f);
        for (int i = start + lane; i < end; i += 32) {
            float v = attn[i];
            attn[i] = (v == 1.0f) ? scale : 0.0f;
        }
    }
}

extern "C" void kernel_launch(void* const* d_in, const int* in_sizes, int n_in,
                              void* d_out, int out_size)
{
    const float* x      = (const float*)d_in[0];
    const int*   batchw = (const int*)d_in[1];

    const int N = in_sizes[1];
    const int D = in_sizes[0] / N;
    int G = (out_size - N) / D;               // layout: [emb (G*D) | attn (N)]
    if (G < 1) G = 1;
    if (G > MAXG) G = MAXG;                   // defensive; never expected

    float* emb  = (float*)d_out;
    float* attn = emb + (size_t)G * D;

    segmax_mark_kernel<<<G, 256>>>(x, batchw, emb, attn, N, G);
    normalize_kernel<<<(G + 7) / 8, 256>>>(attn, G);
}